// round 4
// baseline (speedup 1.0000x reference)
#include <cuda_runtime.h>
#include <cuda_bf16.h>

#define N_RAYS 32768
#define M_G    1024
#define M_PAIRS (M_G / 2)          // 512 gaussian pairs
#define TBL_FLOATS (M_PAIRS * 32)  // 16384 floats = 64 KB
#define SPLITS 8
#define SLOTS  32                  // ray-A slots; ray-B = slot+32 -> 64 rays/block
#define RAYS_PER_BLOCK 64
#define ITERS  (M_PAIRS / SPLITS)  // 64 pair-iterations per thread

// Pair-interleaved coefficient table: pair q, coefficient c (0..15), half h:
//   g_coef[q*32 + c*2 + h] = w_c[2q + h]
// c: 0..3 = C00,C11,C22,C33 | 4..9 = 2C01,2C02,2C03,2C12,2C13,2C23
//    10..13 = l0..l3 | 14 = const (mu^T C mu) | 15 = label
__device__ float g_coef[TBL_FLOATS];

typedef unsigned long long ull;

__device__ __forceinline__ ull pack2(float a, float b) {
    ull r; asm("mov.b64 %0, {%1, %2};" : "=l"(r) : "f"(a), "f"(b)); return r;
}
__device__ __forceinline__ void unpack2(ull v, float& a, float& b) {
    asm("mov.b64 {%0, %1}, %2;" : "=f"(a), "=f"(b) : "l"(v));
}
__device__ __forceinline__ ull fma2(ull a, ull b, ull c) {
    ull d; asm("fma.rn.f32x2 %0, %1, %2, %3;" : "=l"(d) : "l"(a), "l"(b), "l"(c)); return d;
}
__device__ __forceinline__ ull mul2(ull a, ull b) {
    ull d; asm("mul.rn.f32x2 %0, %1, %2;" : "=l"(d) : "l"(a), "l"(b)); return d;
}
__device__ __forceinline__ ull add2(ull a, ull b) {
    ull d; asm("add.rn.f32x2 %0, %1, %2;" : "=l"(d) : "l"(a), "l"(b)); return d;
}

// ---------------------------------------------------------------------------
// Prep: fp32 Gauss-Jordan inverse + one Newton refinement. Folds -0.5*log2(e)
// and the mean into 16 coefficients, written pair-interleaved.
// ---------------------------------------------------------------------------
__global__ void prep_kernel(const float* __restrict__ means,
                            const float* __restrict__ covs,
                            const float* __restrict__ labels) {
    int m = blockIdx.x * blockDim.x + threadIdx.x;
    if (m >= M_G) return;

    float S[4][4], a[4][8];
    #pragma unroll
    for (int i = 0; i < 4; i++)
        #pragma unroll
        for (int j = 0; j < 4; j++) {
            S[i][j] = covs[m * 16 + i * 4 + j];
            a[i][j] = S[i][j];
        }
    #pragma unroll
    for (int i = 0; i < 4; i++)
        #pragma unroll
        for (int j = 0; j < 4; j++) a[i][4 + j] = (i == j) ? 1.0f : 0.0f;

    #pragma unroll
    for (int c = 0; c < 4; c++) {
        float inv = __frcp_rn(a[c][c]);
        #pragma unroll
        for (int j = 0; j < 8; j++) a[c][j] *= inv;
        #pragma unroll
        for (int r = 0; r < 4; r++) {
            if (r == c) continue;
            float f = a[r][c];
            #pragma unroll
            for (int j = 0; j < 8; j++) a[r][j] = fmaf(-f, a[c][j], a[r][j]);
        }
    }
    float X[4][4];
    #pragma unroll
    for (int i = 0; i < 4; i++)
        #pragma unroll
        for (int j = 0; j < 4; j++) X[i][j] = a[i][4 + j];

    // Newton: X <- X * (2I - S*X)
    float T[4][4], Xr[4][4];
    #pragma unroll
    for (int i = 0; i < 4; i++)
        #pragma unroll
        for (int j = 0; j < 4; j++) {
            float s = (i == j) ? 2.0f : 0.0f;
            #pragma unroll
            for (int k = 0; k < 4; k++) s = fmaf(-S[i][k], X[k][j], s);
            T[i][j] = s;
        }
    #pragma unroll
    for (int i = 0; i < 4; i++)
        #pragma unroll
        for (int j = 0; j < 4; j++) {
            float s = 0.0f;
            #pragma unroll
            for (int k = 0; k < 4; k++) s = fmaf(X[i][k], T[k][j], s);
            Xr[i][j] = s;
        }

    const float kk = -0.5f * 1.4426950408889634f;  // -0.5*log2(e)
    float C[4][4];
    #pragma unroll
    for (int i = 0; i < 4; i++)
        #pragma unroll
        for (int j = 0; j < 4; j++) C[i][j] = kk * Xr[i][j];

    float mu[4];
    #pragma unroll
    for (int i = 0; i < 4; i++) mu[i] = means[m * 4 + i];

    float w[16];
    w[0] = C[0][0]; w[1] = C[1][1]; w[2] = C[2][2]; w[3] = C[3][3];
    w[4] = 2.0f * C[0][1]; w[5] = 2.0f * C[0][2]; w[6] = 2.0f * C[0][3];
    w[7] = 2.0f * C[1][2]; w[8] = 2.0f * C[1][3]; w[9] = 2.0f * C[2][3];
    #pragma unroll
    for (int i = 0; i < 4; i++) {
        float s = 0.0f;
        #pragma unroll
        for (int j = 0; j < 4; j++) s = fmaf(C[i][j], mu[j], s);
        w[10 + i] = -2.0f * s;
    }
    float q = 0.0f;
    #pragma unroll
    for (int i = 0; i < 4; i++) {
        float s = 0.0f;
        #pragma unroll
        for (int j = 0; j < 4; j++) s = fmaf(C[i][j], mu[j], s);
        q = fmaf(mu[i], s, q);
    }
    w[14] = q;
    w[15] = labels[m];

    int qp = m >> 1, h = m & 1;
    #pragma unroll
    for (int c = 0; c < 16; c++) g_coef[qp * 32 + c * 2 + h] = w[c];
}

// ---------------------------------------------------------------------------
// Decoder: 256 threads = 32 ray-slots x 8 M-splits; 2 rays/thread.
// Block covers 64 rays; grid = 512; 3 CTAs/SM (24 warps) target.
// Coefficient loads staged 2x LDS.128 to hold regs <= 85.
// ---------------------------------------------------------------------------
extern __shared__ float smem_f[];   // [TBL_FLOATS] table + [512] partials

__global__ void __launch_bounds__(256, 3)
decoder_kernel(const float* __restrict__ origins,
               const float* __restrict__ dirs,
               float* __restrict__ out) {
    const int tid  = threadIdx.x;
    const int slot = tid & (SLOTS - 1);   // 0..31
    const int spl  = tid >> 5;            // 0..7

    // cooperative table load (vectorized)
    {
        const float4* g4 = reinterpret_cast<const float4*>(g_coef);
        float4* s4 = reinterpret_cast<float4*>(smem_f);
        #pragma unroll
        for (int i = 0; i < TBL_FLOATS / 4 / 256; i++)
            s4[tid + i * 256] = g4[tid + i * 256];
    }
    float* s_red = smem_f + TBL_FLOATS;   // [SPLITS][64]
    __syncthreads();

    const int base = blockIdx.x * RAYS_PER_BLOCK;
    const int nA = base + slot;
    const int nB = base + slot + SLOTS;

    const float2 oA = reinterpret_cast<const float2*>(origins)[nA];
    const float2 dA = reinterpret_cast<const float2*>(dirs)[nA];
    const float2 oB = reinterpret_cast<const float2*>(origins)[nB];
    const float2 dB = reinterpret_cast<const float2*>(dirs)[nB];

    const float a0p = oA.x, a1p = oA.y, a2p = dA.x, a3p = dA.y;
    const float b0p = oB.x, b1p = oB.y, b2p = dB.x, b3p = dB.y;

    // duplicated packed monomials, ray A
    const ull AF00 = pack2(a0p*a0p, a0p*a0p), AF11 = pack2(a1p*a1p, a1p*a1p);
    const ull AF22 = pack2(a2p*a2p, a2p*a2p), AF33 = pack2(a3p*a3p, a3p*a3p);
    const ull AF01 = pack2(a0p*a1p, a0p*a1p), AF02 = pack2(a0p*a2p, a0p*a2p);
    const ull AF03 = pack2(a0p*a3p, a0p*a3p), AF12 = pack2(a1p*a2p, a1p*a2p);
    const ull AF13 = pack2(a1p*a3p, a1p*a3p), AF23 = pack2(a2p*a3p, a2p*a3p);
    const ull AP0 = pack2(a0p, a0p), AP1 = pack2(a1p, a1p);
    const ull AP2 = pack2(a2p, a2p), AP3 = pack2(a3p, a3p);
    // ray B
    const ull BF00 = pack2(b0p*b0p, b0p*b0p), BF11 = pack2(b1p*b1p, b1p*b1p);
    const ull BF22 = pack2(b2p*b2p, b2p*b2p), BF33 = pack2(b3p*b3p, b3p*b3p);
    const ull BF01 = pack2(b0p*b1p, b0p*b1p), BF02 = pack2(b0p*b2p, b0p*b2p);
    const ull BF03 = pack2(b0p*b3p, b0p*b3p), BF12 = pack2(b1p*b2p, b1p*b2p);
    const ull BF13 = pack2(b1p*b3p, b1p*b3p), BF23 = pack2(b2p*b3p, b2p*b3p);
    const ull BP0 = pack2(b0p, b0p), BP1 = pack2(b1p, b1p);
    const ull BP2 = pack2(b2p, b2p), BP3 = pack2(b3p, b3p);

    ull accA = pack2(0.0f, 0.0f);
    ull accB = pack2(0.0f, 0.0f);

    const float* tbl = smem_f + spl * ITERS * 32;

    #pragma unroll 1
    for (int q = 0; q < ITERS; q++) {
        const ulonglong2* sp = reinterpret_cast<const ulonglong2*>(tbl + q * 32);

        // stage 1: quad-diagonal coefficients
        ulonglong2 u0 = sp[0];  // C00 | C11
        ulonglong2 u1 = sp[1];  // C22 | C33
        ull x0 = mul2(u0.x, AF00);
        ull x1 = mul2(u0.y, AF11);
        ull y0 = mul2(u0.x, BF00);
        ull y1 = mul2(u0.y, BF11);
        x0 = fma2(u1.x, AF22, x0);
        x1 = fma2(u1.y, AF33, x1);
        y0 = fma2(u1.x, BF22, y0);
        y1 = fma2(u1.y, BF33, y1);

        // stage 2: cross terms 01,02,03,12
        u0 = sp[2];  u1 = sp[3];
        x0 = fma2(u0.x, AF01, x0);
        x1 = fma2(u0.y, AF02, x1);
        y0 = fma2(u0.x, BF01, y0);
        y1 = fma2(u0.y, BF02, y1);
        x0 = fma2(u1.x, AF03, x0);
        x1 = fma2(u1.y, AF12, x1);
        y0 = fma2(u1.x, BF03, y0);
        y1 = fma2(u1.y, BF12, y1);

        // stage 3: cross 13,23 + linear l0,l1
        u0 = sp[4];  u1 = sp[5];
        x0 = fma2(u0.x, AF13, x0);
        x1 = fma2(u0.y, AF23, x1);
        y0 = fma2(u0.x, BF13, y0);
        y1 = fma2(u0.y, BF23, y1);
        x0 = fma2(u1.x, AP0, x0);
        x1 = fma2(u1.y, AP1, x1);
        y0 = fma2(u1.x, BP0, y0);
        y1 = fma2(u1.y, BP1, y1);

        // stage 4: linear l2,l3 + const + label
        u0 = sp[6];  u1 = sp[7];
        x0 = fma2(u0.x, AP2, x0);
        x1 = fma2(u0.y, AP3, x1);
        y0 = fma2(u0.x, BP2, y0);
        y1 = fma2(u0.y, BP3, y1);
        x0 = add2(x0, u1.x);           // + const
        y0 = add2(y0, u1.x);
        const ull tA = add2(x0, x1);
        const ull tB = add2(y0, y1);

        float ta0, ta1, tb0, tb1;
        unpack2(tA, ta0, ta1);
        unpack2(tB, tb0, tb1);
        float ea0, ea1, eb0, eb1;
        asm("ex2.approx.ftz.f32 %0, %1;" : "=f"(ea0) : "f"(ta0));
        asm("ex2.approx.ftz.f32 %0, %1;" : "=f"(ea1) : "f"(ta1));
        asm("ex2.approx.ftz.f32 %0, %1;" : "=f"(eb0) : "f"(tb0));
        asm("ex2.approx.ftz.f32 %0, %1;" : "=f"(eb1) : "f"(tb1));
        accA = fma2(u1.y, pack2(ea0, ea1), accA);
        accB = fma2(u1.y, pack2(eb0, eb1), accB);
    }

    float sa0, sa1, sb0, sb1;
    unpack2(accA, sa0, sa1);
    unpack2(accB, sb0, sb1);
    s_red[spl * RAYS_PER_BLOCK + slot]         = sa0 + sa1;
    s_red[spl * RAYS_PER_BLOCK + SLOTS + slot] = sb0 + sb1;
    __syncthreads();

    if (tid < RAYS_PER_BLOCK) {
        float accT = 0.0f;
        #pragma unroll
        for (int s = 0; s < SPLITS; s++)
            accT += s_red[s * RAYS_PER_BLOCK + tid];
        const float z = -accT * 1.4426950408889634f;
        float em;
        asm("ex2.approx.ftz.f32 %0, %1;" : "=f"(em) : "f"(z));
        float prob;
        asm("rcp.approx.ftz.f32 %0, %1;" : "=f"(prob) : "f"(1.0f + em));
        out[base + tid] = prob;
    }
}

// ---------------------------------------------------------------------------
extern "C" void kernel_launch(void* const* d_in, const int* in_sizes, int n_in,
                              void* d_out, int out_size) {
    const float* origins    = (const float*)d_in[0];
    const float* directions = (const float*)d_in[1];
    const float* means      = (const float*)d_in[2];
    const float* covs       = (const float*)d_in[3];
    const float* labels     = (const float*)d_in[4];
    float* out = (float*)d_out;

    prep_kernel<<<32, 32>>>(means, covs, labels);

    const int smem_bytes = (TBL_FLOATS + 512) * (int)sizeof(float);
    cudaFuncSetAttribute(decoder_kernel,
                         cudaFuncAttributeMaxDynamicSharedMemorySize, smem_bytes);
    decoder_kernel<<<N_RAYS / RAYS_PER_BLOCK, 256, smem_bytes>>>(origins, directions, out);
}